// round 7
// baseline (speedup 1.0000x reference)
#include <cuda_runtime.h>
#include <cuda_bf16.h>
#include <stdint.h>

// ---------------- problem constants ----------------
#define Bn 4
#define Tn 4096
#define Dn 2048
#define Hn 256
#define Wn 4
#define Mn (Bn * Tn)        // 16384
#define N2 (Dn * Wn)        // 8192

// Only intermediate: H = silu(X @ W1) as bf16 hi/lo splits.
__device__ __nv_bfloat16 g_hhi[(size_t)Mn * Hn];
__device__ __nv_bfloat16 g_hlo[(size_t)Mn * Hn];

__device__ __forceinline__ float silu_f(float v) { return v / (1.0f + __expf(-v)); }

__device__ __forceinline__ void split2(float v, __nv_bfloat16& h, __nv_bfloat16& l) {
    h = __float2bfloat16_rn(v);
    l = __float2bfloat16_rn(v - __bfloat162float(h));
}

__device__ __forceinline__ void mma_bf16(float* d, const uint32_t* a,
                                         uint32_t b0, uint32_t b1) {
    asm volatile(
        "mma.sync.aligned.m16n8k16.row.col.f32.bf16.bf16.f32 "
        "{%0,%1,%2,%3}, {%4,%5,%6,%7}, {%8,%9}, {%0,%1,%2,%3};"
        : "+f"(d[0]), "+f"(d[1]), "+f"(d[2]), "+f"(d[3])
        : "r"(a[0]), "r"(a[1]), "r"(a[2]), "r"(a[3]), "r"(b0), "r"(b1));
}

// ---------------- smem geometry (identical to R6) ----------------
// CTA 128(M) x 128(N), K chunk 16. 8 warps: wm = wid&3 (M 4x32), wn = wid>>2 (N 2x64).
// smem: [2 buf][4 halves: Ahi,Alo,Bhi,Blo][128 rows x ROWPAD] bf16 = 48KB.
#define ROWPAD 24
#define HALF_E (128 * ROWPAD)

// ---------------- fragment compute (byte-identical to R6) ----------------
// PTX m16n8k16 fragment spec. gid=lane>>2, tig=lane&3.
__device__ __forceinline__ void compute_chunk(
    const __nv_bfloat16* __restrict__ sbuf, int lane, int wm, int wn, float acc[2][8][4])
{
    const int gid = lane >> 2, tig = lane & 3;
    const __nv_bfloat16* sAh = sbuf;
    const __nv_bfloat16* sAl = sbuf + HALF_E;
    const __nv_bfloat16* sBh = sbuf + 2 * HALF_E;
    const __nv_bfloat16* sBl = sbuf + 3 * HALF_E;

    uint32_t ah[2][4], al[2][4];
    #pragma unroll
    for (int mt = 0; mt < 2; mt++) {
        const int r = wm * 32 + mt * 16 + gid;
        const int c = tig * 2;
        ah[mt][0] = *(const uint32_t*)&sAh[r * ROWPAD + c];
        ah[mt][1] = *(const uint32_t*)&sAh[(r + 8) * ROWPAD + c];
        ah[mt][2] = *(const uint32_t*)&sAh[r * ROWPAD + c + 8];
        ah[mt][3] = *(const uint32_t*)&sAh[(r + 8) * ROWPAD + c + 8];
        al[mt][0] = *(const uint32_t*)&sAl[r * ROWPAD + c];
        al[mt][1] = *(const uint32_t*)&sAl[(r + 8) * ROWPAD + c];
        al[mt][2] = *(const uint32_t*)&sAl[r * ROWPAD + c + 8];
        al[mt][3] = *(const uint32_t*)&sAl[(r + 8) * ROWPAD + c + 8];
    }

    #pragma unroll
    for (int nt = 0; nt < 8; nt++) {
        const int n = wn * 64 + nt * 8 + gid;
        const int c = tig * 2;
        uint32_t bh0 = *(const uint32_t*)&sBh[n * ROWPAD + c];
        uint32_t bh1 = *(const uint32_t*)&sBh[n * ROWPAD + c + 8];
        uint32_t bl0 = *(const uint32_t*)&sBl[n * ROWPAD + c];
        uint32_t bl1 = *(const uint32_t*)&sBl[n * ROWPAD + c + 8];
        #pragma unroll
        for (int mt = 0; mt < 2; mt++) {
            float* d = acc[mt][nt];
            mma_bf16(d, ah[mt], bh0, bh1);
            mma_bf16(d, ah[mt], bl0, bl1);
            mma_bf16(d, al[mt], bh0, bh1);
        }
    }
}

// ---------------- staging: fp32 -> split -> smem, no prep kernels ----------------
// A (fp32 X): 128 rows x 16 k, 2 float4 per thread.
// B (fp32 W, [K, N] row-major = col-major operand): 16 k x 128 n, 2 float4 per
// thread, scattered into smem layout [n][k] (same layout compute_chunk expects).
struct G1Stage { float4 a0, a1, b0, b1; };

__device__ __forceinline__ G1Stage g1_ldg(
    const float* __restrict__ X, int lda, const float* __restrict__ W, int ldw,
    int m0, int n0, int k0, int tid)
{
    G1Stage s;
    const int i0 = tid * 2, i1 = tid * 2 + 1;
    s.a0 = *(const float4*)(X + (size_t)(m0 + (i0 >> 2)) * lda + k0 + (i0 & 3) * 4);
    s.a1 = *(const float4*)(X + (size_t)(m0 + (i1 >> 2)) * lda + k0 + (i1 & 3) * 4);
    s.b0 = *(const float4*)(W + (size_t)(k0 + (i0 >> 5)) * ldw + n0 + (i0 & 31) * 4);
    s.b1 = *(const float4*)(W + (size_t)(k0 + (i1 >> 5)) * ldw + n0 + (i1 & 31) * 4);
    return s;
}

__device__ __forceinline__ void g1_sts_a(__nv_bfloat16* sbuf, int idx, float4 v) {
    const int off = (idx >> 2) * ROWPAD + (idx & 3) * 4;
    __nv_bfloat16 h0, l0, h1, l1, h2, l2, h3, l3;
    split2(v.x, h0, l0); split2(v.y, h1, l1);
    split2(v.z, h2, l2); split2(v.w, h3, l3);
    *(__nv_bfloat162*)(sbuf + off)              = __nv_bfloat162(h0, h1);
    *(__nv_bfloat162*)(sbuf + off + 2)          = __nv_bfloat162(h2, h3);
    *(__nv_bfloat162*)(sbuf + HALF_E + off)     = __nv_bfloat162(l0, l1);
    *(__nv_bfloat162*)(sbuf + HALF_E + off + 2) = __nv_bfloat162(l2, l3);
}

__device__ __forceinline__ void g1_sts_b(__nv_bfloat16* sBh, int idx, float4 v) {
    const int krow = idx >> 5, c4 = (idx & 31) * 4;
    __nv_bfloat16 h, l;
    split2(v.x, h, l); sBh[(c4 + 0) * ROWPAD + krow] = h; sBh[HALF_E + (c4 + 0) * ROWPAD + krow] = l;
    split2(v.y, h, l); sBh[(c4 + 1) * ROWPAD + krow] = h; sBh[HALF_E + (c4 + 1) * ROWPAD + krow] = l;
    split2(v.z, h, l); sBh[(c4 + 2) * ROWPAD + krow] = h; sBh[HALF_E + (c4 + 2) * ROWPAD + krow] = l;
    split2(v.w, h, l); sBh[(c4 + 3) * ROWPAD + krow] = h; sBh[HALF_E + (c4 + 3) * ROWPAD + krow] = l;
}

__device__ __forceinline__ void g1_sts(__nv_bfloat16* sbuf, const G1Stage& s, int tid) {
    g1_sts_a(sbuf, tid * 2, s.a0);
    g1_sts_a(sbuf, tid * 2 + 1, s.a1);
    g1_sts_b(sbuf + 2 * HALF_E, tid * 2, s.b0);
    g1_sts_b(sbuf + 2 * HALF_E, tid * 2 + 1, s.b1);
}

// ---------------- GEMM1: H = silu(X @ W1) -> bf16 hi/lo (no preps) ----------------
__global__ __launch_bounds__(256, 2) void gemm1_mma_kernel(
    const float* __restrict__ X, const float* __restrict__ W1)
{
    __shared__ __align__(16) __nv_bfloat16 sm[2][4 * HALF_E];
    const int tid = threadIdx.x, lane = tid & 31, wid = tid >> 5;
    const int wm = wid & 3, wn = wid >> 2;
    const int m0 = blockIdx.y * 128, n0 = blockIdx.x * 128;

    float acc[2][8][4] = {};
    {
        const int CHUNKS = Dn / 16;
        G1Stage st = g1_ldg(X, Dn, W1, Hn, m0, n0, 0, tid);
        g1_sts(&sm[0][0], st, tid);
        __syncthreads();
        for (int c = 0; c < CHUNKS; c++) {
            const bool has_next = (c + 1 < CHUNKS);
            if (has_next) st = g1_ldg(X, Dn, W1, Hn, m0, n0, (c + 1) * 16, tid);
            compute_chunk(&sm[c & 1][0], lane, wm, wn, acc);
            if (has_next) {
                g1_sts(&sm[(c + 1) & 1][0], st, tid);
                __syncthreads();
            }
        }
    }

    #pragma unroll
    for (int mt = 0; mt < 2; mt++) {
        const int r = m0 + wm * 32 + mt * 16 + (lane >> 2);
        #pragma unroll
        for (int nt = 0; nt < 8; nt++) {
            const int c = n0 + wn * 64 + nt * 8 + (lane & 3) * 2;
            float f0 = silu_f(acc[mt][nt][0]);
            float f1 = silu_f(acc[mt][nt][1]);
            float f2 = silu_f(acc[mt][nt][2]);
            float f3 = silu_f(acc[mt][nt][3]);
            __nv_bfloat16 h0, l0, h1, l1, h2, l2, h3, l3;
            split2(f0, h0, l0); split2(f1, h1, l1);
            split2(f2, h2, l2); split2(f3, h3, l3);
            *(__nv_bfloat162*)(g_hhi + (size_t)r * Hn + c)       = __nv_bfloat162(h0, h1);
            *(__nv_bfloat162*)(g_hlo + (size_t)r * Hn + c)       = __nv_bfloat162(l0, l1);
            *(__nv_bfloat162*)(g_hhi + (size_t)(r + 8) * Hn + c) = __nv_bfloat162(h2, h3);
            *(__nv_bfloat162*)(g_hlo + (size_t)(r + 8) * Hn + c) = __nv_bfloat162(l2, l3);
        }
    }
}

// ---------------- GEMM2 staging: A from g_h (bf16), B from W2 (fp32) ----------------
struct G2Stage { uint4 ah, al; float4 b0, b1; };

__device__ __forceinline__ G2Stage g2_ldg(
    const float* __restrict__ W2, int m0, int n0, int k0, int tid)
{
    G2Stage s;
    const int row = tid >> 1, sh = tid & 1;
    const size_t aoff = (size_t)(m0 + row) * Hn + k0 + sh * 8;
    s.ah = *(const uint4*)(g_hhi + aoff);
    s.al = *(const uint4*)(g_hlo + aoff);
    const int i0 = tid * 2, i1 = tid * 2 + 1;
    s.b0 = *(const float4*)(W2 + (size_t)(k0 + (i0 >> 5)) * N2 + n0 + (i0 & 31) * 4);
    s.b1 = *(const float4*)(W2 + (size_t)(k0 + (i1 >> 5)) * N2 + n0 + (i1 & 31) * 4);
    return s;
}

__device__ __forceinline__ void g2_sts(__nv_bfloat16* sbuf, const G2Stage& s, int tid) {
    const int row = tid >> 1, sh = tid & 1;
    const int off = row * ROWPAD + sh * 8;
    *(uint4*)(sbuf + off)          = s.ah;
    *(uint4*)(sbuf + HALF_E + off) = s.al;
    g1_sts_b(sbuf + 2 * HALF_E, tid * 2, s.b0);
    g1_sts_b(sbuf + 2 * HALF_E, tid * 2 + 1, s.b1);
}

// ---------------- GEMM2: flat = H @ W2 + b2; fused conv + silu ----------------
__global__ __launch_bounds__(256, 2) void gemm2_mma_kernel(
    const float* __restrict__ X, const float* __restrict__ W2,
    const float* __restrict__ B2, float* __restrict__ OUT)
{
    __shared__ __align__(16) __nv_bfloat16 sm[2][4 * HALF_E];
    const int tid = threadIdx.x, lane = tid & 31, wid = tid >> 5;
    const int wm = wid & 3, wn = wid >> 2;
    const int m0 = blockIdx.y * 128, n0 = blockIdx.x * 128;

    float acc[2][8][4] = {};
    {
        const int CHUNKS = Hn / 16;
        G2Stage st = g2_ldg(W2, m0, n0, 0, tid);
        g2_sts(&sm[0][0], st, tid);
        __syncthreads();
        for (int c = 0; c < CHUNKS; c++) {
            const bool has_next = (c + 1 < CHUNKS);
            if (has_next) st = g2_ldg(W2, m0, n0, (c + 1) * 16, tid);
            compute_chunk(&sm[c & 1][0], lane, wm, wn, acc);
            if (has_next) {
                g2_sts(&sm[(c + 1) & 1][0], st, tid);
                __syncthreads();
            }
        }
    }

    // Epilogue: bias + quad-shuffle gather of 4-tap kernels + causal conv + silu.
    const int q = lane & 3;
    #pragma unroll
    for (int mt = 0; mt < 2; mt++) {
        const int rbase = m0 + wm * 32 + mt * 16 + (lane >> 2);
        #pragma unroll
        for (int nt = 0; nt < 8; nt++) {
            const int colb = n0 + wn * 64 + nt * 8;
            const int col0 = colb + q * 2;
            const float bb0 = B2[col0], bb1 = B2[col0 + 1];
            float c0 = acc[mt][nt][0] + bb0;
            float c1 = acc[mt][nt][1] + bb1;
            float c2 = acc[mt][nt][2] + bb0;
            float c3 = acc[mt][nt][3] + bb1;
            float o0 = __shfl_xor_sync(0xffffffffu, c0, 1);
            float o1 = __shfl_xor_sync(0xffffffffu, c1, 1);
            float o2 = __shfl_xor_sync(0xffffffffu, c2, 1);
            float o3 = __shfl_xor_sync(0xffffffffu, c3, 1);

            float k0, k1, k2, k3;
            int row;
            if ((q & 1) == 0) { row = rbase;     k0 = c0; k1 = c1; k2 = o0; k3 = o1; }
            else              { row = rbase + 8; k0 = o2; k1 = o3; k2 = c2; k3 = c3; }
            const int d = (colb >> 2) + (q >> 1);

            const int tt = row & (Tn - 1);
            const int brow = row - tt;
            float o = 0.0f;
            {
                int t = tt - 3;
                float xv = (t >= 0) ? X[(size_t)(brow + t) * Dn + d] : 0.0f;
                o += k0 * xv;
                t = tt - 2;
                xv = (t >= 0) ? X[(size_t)(brow + t) * Dn + d] : 0.0f;
                o += k1 * xv;
                t = tt - 1;
                xv = (t >= 0) ? X[(size_t)(brow + t) * Dn + d] : 0.0f;
                o += k2 * xv;
                o += k3 * X[(size_t)(brow + tt) * Dn + d];
            }
            OUT[(size_t)row * Dn + d] = silu_f(o);
        }
    }
}

// ---------------- launch ----------------
extern "C" void kernel_launch(void* const* d_in, const int* in_sizes, int n_in,
                              void* d_out, int out_size) {
    const float* x  = (const float*)d_in[0];   // [4,4096,2048]
    const float* w1 = (const float*)d_in[1];   // [2048,256]
    const float* w2 = (const float*)d_in[2];   // [256,8192]
    const float* b2 = (const float*)d_in[3];   // [8192]
    float* out = (float*)d_out;

    gemm1_mma_kernel<<<dim3(Hn / 128, Mn / 128), 256>>>(x, w1);
    gemm2_mma_kernel<<<dim3(N2 / 128, Mn / 128), 256>>>(x, w2, b2, out);
}

// round 8
// speedup vs baseline: 1.7370x; 1.7370x over previous
#include <cuda_runtime.h>
#include <cuda_bf16.h>
#include <stdint.h>

// ---------------- problem constants ----------------
#define Bn 4
#define Tn 4096
#define Dn 2048
#define Hn 256
#define Wn 4
#define Mn (Bn * Tn)        // 16384
#define N2 (Dn * Wn)        // 8192

// Only intermediate: H = silu(X @ W1) as bf16 hi/lo splits.
__device__ __nv_bfloat16 g_hhi[(size_t)Mn * Hn];
__device__ __nv_bfloat16 g_hlo[(size_t)Mn * Hn];

__device__ __forceinline__ float silu_f(float v) { return v / (1.0f + __expf(-v)); }

__device__ __forceinline__ void mma_bf16(float* d, const uint32_t* a,
                                         uint32_t b0, uint32_t b1) {
    asm volatile(
        "mma.sync.aligned.m16n8k16.row.col.f32.bf16.bf16.f32 "
        "{%0,%1,%2,%3}, {%4,%5,%6,%7}, {%8,%9}, {%0,%1,%2,%3};"
        : "+f"(d[0]), "+f"(d[1]), "+f"(d[2]), "+f"(d[3])
        : "r"(a[0]), "r"(a[1]), "r"(a[2]), "r"(a[3]), "r"(b0), "r"(b1));
}

__device__ __forceinline__ void split_pair(float a, float b, uint32_t& hi, uint32_t& lo) {
    __nv_bfloat16 ha = __float2bfloat16_rn(a), hb = __float2bfloat16_rn(b);
    __nv_bfloat162 hw(ha, hb);
    __nv_bfloat162 lw(__float2bfloat16_rn(a - __bfloat162float(ha)),
                      __float2bfloat16_rn(b - __bfloat162float(hb)));
    hi = *(uint32_t*)&hw;
    lo = *(uint32_t*)&lw;
}

// ---------------- packed smem layout ----------------
// Chunk = k32. 4 half-sections: Ahi, Alo, Bhi, Blo.
// Half-section = [s(2)][row(128)][16 elems], elems hold 4 word-pairs:
// pair q = tig stores words (t = s*8+q, t+4) adjacent -> LDS.64, conflict-free.
#define KC 32
#define SBLK 2048                    // elems per s-block (128 rows x 16)
#define SEC_E (2 * SBLK)             // 4096 elems per half-section (8KB)
#define CHUNK_E (4 * SEC_E)          // 16384 elems per buffer (32KB)
#define SMEM_BYTES (2 * CHUNK_E * 2) // 65536

// Write 8 words (tw = 0..7 of sub-chunk h) as 4 paired 64-bit stores.
__device__ __forceinline__ void sts_pairs(__nv_bfloat16* sec, int row, int h,
                                          const uint32_t* w) {
    __nv_bfloat16* p = sec + h * SBLK + row * 16;
    #pragma unroll
    for (int j = 0; j < 4; j++) {
        uint2 u; u.x = w[j]; u.y = w[j + 4];
        *(uint2*)(p + j * 4) = u;
    }
}

// ---------------- fragment compute: one k16 sub-chunk ----------------
__device__ __forceinline__ void compute_sub(const __nv_bfloat16* __restrict__ sbuf, int s,
                                            int lane, int wm, int wn, float acc[2][8][4]) {
    const int gid = lane >> 2, tig = lane & 3;
    const __nv_bfloat16* sA  = sbuf + s * SBLK;
    const __nv_bfloat16* sAl = sA + SEC_E;
    const __nv_bfloat16* sB  = sbuf + 2 * SEC_E + s * SBLK;
    const __nv_bfloat16* sBl = sB + SEC_E;
    const int qo = tig * 4;

    uint32_t ah[2][4], al[2][4];
    #pragma unroll
    for (int mt = 0; mt < 2; mt++) {
        const int r = wm * 32 + mt * 16 + gid;
        uint2 x0 = *(const uint2*)(sA + r * 16 + qo);
        uint2 x1 = *(const uint2*)(sA + (r + 8) * 16 + qo);
        ah[mt][0] = x0.x; ah[mt][1] = x1.x; ah[mt][2] = x0.y; ah[mt][3] = x1.y;
        uint2 y0 = *(const uint2*)(sAl + r * 16 + qo);
        uint2 y1 = *(const uint2*)(sAl + (r + 8) * 16 + qo);
        al[mt][0] = y0.x; al[mt][1] = y1.x; al[mt][2] = y0.y; al[mt][3] = y1.y;
    }

    #pragma unroll
    for (int nt = 0; nt < 8; nt++) {
        const int n = wn * 64 + nt * 8 + gid;
        uint2 bh = *(const uint2*)(sB + n * 16 + qo);
        uint2 bl = *(const uint2*)(sBl + n * 16 + qo);
        #pragma unroll
        for (int mt = 0; mt < 2; mt++) {
            float* d = acc[mt][nt];
            mma_bf16(d, ah[mt], bh.x, bh.y);
            mma_bf16(d, ah[mt], bl.x, bl.y);
            mma_bf16(d, al[mt], bh.x, bh.y);
        }
    }
}

// ---------------- GEMM1: H = silu(X @ W1) -> bf16 hi/lo ----------------
__global__ __launch_bounds__(256, 2) void gemm1_mma_kernel(
    const float* __restrict__ X, const float* __restrict__ W1)
{
    extern __shared__ __align__(16) __nv_bfloat16 sm[];
    const int tid = threadIdx.x, lane = tid & 31, wid = tid >> 5;
    const int wm = wid & 3, wn = wid >> 2;
    const int m0 = blockIdx.y * 128, n0 = blockIdx.x * 128;

    const int ar = tid >> 1, ahalf = tid & 1;   // A stager: row, k-half
    const int bn = tid >> 1, bhalf = tid & 1;   // B stager: n-row, k-half

    float4 va[4];      // raw A fp32 (16 vals)
    float fb[16];      // raw B fp32

    float acc[2][8][4] = {};
    const int CH = Dn / KC;

    #define G1_LDG(c) {                                                          \
        const float* ap = X + (size_t)(m0 + ar) * Dn + (c) * KC + ahalf * 16;    \
        va[0] = *(const float4*)(ap);                                            \
        va[1] = *(const float4*)(ap + 4);                                        \
        va[2] = *(const float4*)(ap + 8);                                        \
        va[3] = *(const float4*)(ap + 12);                                       \
        const float* bp = W1 + (size_t)((c) * KC + bhalf * 16) * Hn + n0 + bn;   \
        _Pragma("unroll")                                                        \
        for (int kk = 0; kk < 16; kk++) fb[kk] = bp[(size_t)kk * Hn];            \
    }

    #define G1_STS(buf) {                                                        \
        __nv_bfloat16* base = sm + (buf) * CHUNK_E;                              \
        uint32_t whi[8], wlo[8];                                                 \
        _Pragma("unroll")                                                        \
        for (int j = 0; j < 4; j++) {                                            \
            split_pair(va[j].x, va[j].y, whi[2*j], wlo[2*j]);                    \
            split_pair(va[j].z, va[j].w, whi[2*j+1], wlo[2*j+1]);                \
        }                                                                        \
        sts_pairs(base,         ar, ahalf, whi);                                 \
        sts_pairs(base + SEC_E, ar, ahalf, wlo);                                 \
        _Pragma("unroll")                                                        \
        for (int tw = 0; tw < 8; tw++)                                           \
            split_pair(fb[2*tw], fb[2*tw+1], whi[tw], wlo[tw]);                  \
        sts_pairs(base + 2*SEC_E, bn, bhalf, whi);                               \
        sts_pairs(base + 3*SEC_E, bn, bhalf, wlo);                               \
    }

    G1_LDG(0);
    G1_STS(0);
    __syncthreads();

    for (int c = 0; c < CH; c++) {
        const bool hn = (c + 1 < CH);
        if (hn) G1_LDG(c + 1);
        compute_sub(sm + (c & 1) * CHUNK_E, 0, lane, wm, wn, acc);
        if (hn) G1_STS((c + 1) & 1);
        compute_sub(sm + (c & 1) * CHUNK_E, 1, lane, wm, wn, acc);
        __syncthreads();
    }

    // Epilogue (verbatim R7): silu -> bf16 hi/lo split of H.
    #pragma unroll
    for (int mt = 0; mt < 2; mt++) {
        const int r = m0 + wm * 32 + mt * 16 + (lane >> 2);
        #pragma unroll
        for (int nt = 0; nt < 8; nt++) {
            const int c = n0 + wn * 64 + nt * 8 + (lane & 3) * 2;
            float f0 = silu_f(acc[mt][nt][0]);
            float f1 = silu_f(acc[mt][nt][1]);
            float f2 = silu_f(acc[mt][nt][2]);
            float f3 = silu_f(acc[mt][nt][3]);
            uint32_t h01, l01, h23, l23;
            split_pair(f0, f1, h01, l01);
            split_pair(f2, f3, h23, l23);
            *(uint32_t*)(g_hhi + (size_t)r * Hn + c)       = h01;
            *(uint32_t*)(g_hlo + (size_t)r * Hn + c)       = l01;
            *(uint32_t*)(g_hhi + (size_t)(r + 8) * Hn + c) = h23;
            *(uint32_t*)(g_hlo + (size_t)(r + 8) * Hn + c) = l23;
        }
    }
}

// ---------------- GEMM2: flat = H @ W2 + b2; fused conv + silu ----------------
__global__ __launch_bounds__(256, 2) void gemm2_mma_kernel(
    const float* __restrict__ X, const float* __restrict__ W2,
    const float* __restrict__ B2, float* __restrict__ OUT)
{
    extern __shared__ __align__(16) __nv_bfloat16 sm[];
    const int tid = threadIdx.x, lane = tid & 31, wid = tid >> 5;
    const int wm = wid & 3, wn = wid >> 2;
    const int m0 = blockIdx.y * 128, n0 = blockIdx.x * 128;

    const int ar = tid >> 1, ahalf = tid & 1;
    const int bn = tid >> 1, bhalf = tid & 1;

    uint4 ua0, ua1, ul0, ul1;   // raw A bf16 (hi: words 0..3 / 4..7, lo same)
    float fb[16];

    float acc[2][8][4] = {};
    const int CH = Hn / KC;   // 8

    #define G2_LDG(c) {                                                          \
        const size_t aoff = (size_t)(m0 + ar) * Hn + (c) * KC + ahalf * 16;      \
        ua0 = *(const uint4*)(g_hhi + aoff);                                     \
        ua1 = *(const uint4*)(g_hhi + aoff + 8);                                 \
        ul0 = *(const uint4*)(g_hlo + aoff);                                     \
        ul1 = *(const uint4*)(g_hlo + aoff + 8);                                 \
        const float* bp = W2 + (size_t)((c) * KC + bhalf * 16) * N2 + n0 + bn;   \
        _Pragma("unroll")                                                        \
        for (int kk = 0; kk < 16; kk++) fb[kk] = bp[(size_t)kk * N2];            \
    }

    #define G2_STS(buf) {                                                        \
        __nv_bfloat16* base = sm + (buf) * CHUNK_E;                              \
        __nv_bfloat16* ph = base + ahalf * SBLK + ar * 16;                       \
        *(uint2*)(ph + 0)  = make_uint2(ua0.x, ua1.x);                           \
        *(uint2*)(ph + 4)  = make_uint2(ua0.y, ua1.y);                           \
        *(uint2*)(ph + 8)  = make_uint2(ua0.z, ua1.z);                           \
        *(uint2*)(ph + 12) = make_uint2(ua0.w, ua1.w);                           \
        __nv_bfloat16* pl = base + SEC_E + ahalf * SBLK + ar * 16;               \
        *(uint2*)(pl + 0)  = make_uint2(ul0.x, ul1.x);                           \
        *(uint2*)(pl + 4)  = make_uint2(ul0.y, ul1.y);                           \
        *(uint2*)(pl + 8)  = make_uint2(ul0.z, ul1.z);                           \
        *(uint2*)(pl + 12) = make_uint2(ul0.w, ul1.w);                           \
        uint32_t whi[8], wlo[8];                                                 \
        _Pragma("unroll")                                                        \
        for (int tw = 0; tw < 8; tw++)                                           \
            split_pair(fb[2*tw], fb[2*tw+1], whi[tw], wlo[tw]);                  \
        sts_pairs(base + 2*SEC_E, bn, bhalf, whi);                               \
        sts_pairs(base + 3*SEC_E, bn, bhalf, wlo);                               \
    }

    G2_LDG(0);
    G2_STS(0);
    __syncthreads();

    for (int c = 0; c < CH; c++) {
        const bool hn = (c + 1 < CH);
        if (hn) G2_LDG(c + 1);
        compute_sub(sm + (c & 1) * CHUNK_E, 0, lane, wm, wn, acc);
        if (hn) G2_STS((c + 1) & 1);
        compute_sub(sm + (c & 1) * CHUNK_E, 1, lane, wm, wn, acc);
        __syncthreads();
    }

    // Epilogue (verbatim R7): bias + quad-shuffle gather + causal conv + silu.
    const int q = lane & 3;
    #pragma unroll
    for (int mt = 0; mt < 2; mt++) {
        const int rbase = m0 + wm * 32 + mt * 16 + (lane >> 2);
        #pragma unroll
        for (int nt = 0; nt < 8; nt++) {
            const int colb = n0 + wn * 64 + nt * 8;
            const int col0 = colb + q * 2;
            const float bb0 = B2[col0], bb1 = B2[col0 + 1];
            float c0 = acc[mt][nt][0] + bb0;
            float c1 = acc[mt][nt][1] + bb1;
            float c2 = acc[mt][nt][2] + bb0;
            float c3 = acc[mt][nt][3] + bb1;
            float o0 = __shfl_xor_sync(0xffffffffu, c0, 1);
            float o1 = __shfl_xor_sync(0xffffffffu, c1, 1);
            float o2 = __shfl_xor_sync(0xffffffffu, c2, 1);
            float o3 = __shfl_xor_sync(0xffffffffu, c3, 1);

            float k0, k1, k2, k3;
            int row;
            if ((q & 1) == 0) { row = rbase;     k0 = c0; k1 = c1; k2 = o0; k3 = o1; }
            else              { row = rbase + 8; k0 = o2; k1 = o3; k2 = c2; k3 = c3; }
            const int d = (colb >> 2) + (q >> 1);

            const int tt = row & (Tn - 1);
            const int brow = row - tt;
            float o = 0.0f;
            {
                int t = tt - 3;
                float xv = (t >= 0) ? X[(size_t)(brow + t) * Dn + d] : 0.0f;
                o += k0 * xv;
                t = tt - 2;
                xv = (t >= 0) ? X[(size_t)(brow + t) * Dn + d] : 0.0f;
                o += k1 * xv;
                t = tt - 1;
                xv = (t >= 0) ? X[(size_t)(brow + t) * Dn + d] : 0.0f;
                o += k2 * xv;
                o += k3 * X[(size_t)(brow + tt) * Dn + d];
            }
            OUT[(size_t)row * Dn + d] = silu_f(o);
        }
    }
}

// ---------------- launch ----------------
extern "C" void kernel_launch(void* const* d_in, const int* in_sizes, int n_in,
                              void* d_out, int out_size) {
    const float* x  = (const float*)d_in[0];   // [4,4096,2048]
    const float* w1 = (const float*)d_in[1];   // [2048,256]
    const float* w2 = (const float*)d_in[2];   // [256,8192]
    const float* b2 = (const float*)d_in[3];   // [8192]
    float* out = (float*)d_out;

    cudaFuncSetAttribute(gemm1_mma_kernel,
                         cudaFuncAttributeMaxDynamicSharedMemorySize, SMEM_BYTES);
    cudaFuncSetAttribute(gemm2_mma_kernel,
                         cudaFuncAttributeMaxDynamicSharedMemorySize, SMEM_BYTES);

    gemm1_mma_kernel<<<dim3(Hn / 128, Mn / 128), 256, SMEM_BYTES>>>(x, w1);
    gemm2_mma_kernel<<<dim3(N2 / 128, Mn / 128), 256, SMEM_BYTES>>>(x, w2, b2, out);
}

// round 9
// speedup vs baseline: 2.0601x; 1.1861x over previous
#include <cuda_runtime.h>
#include <cuda_bf16.h>
#include <stdint.h>

// ---------------- problem constants ----------------
#define Bn 4
#define Tn 4096
#define Dn 2048
#define Hn 256
#define Wn 4
#define Mn (Bn * Tn)        // 16384
#define N2 (Dn * Wn)        // 8192

// Only intermediate: H = silu(X @ W1) as bf16 hi/lo splits.
__device__ __nv_bfloat16 g_hhi[(size_t)Mn * Hn];
__device__ __nv_bfloat16 g_hlo[(size_t)Mn * Hn];

__device__ __forceinline__ float silu_f(float v) { return v / (1.0f + __expf(-v)); }

__device__ __forceinline__ void mma_bf16(float* d, const uint32_t* a,
                                         uint32_t b0, uint32_t b1) {
    asm volatile(
        "mma.sync.aligned.m16n8k16.row.col.f32.bf16.bf16.f32 "
        "{%0,%1,%2,%3}, {%4,%5,%6,%7}, {%8,%9}, {%0,%1,%2,%3};"
        : "+f"(d[0]), "+f"(d[1]), "+f"(d[2]), "+f"(d[3])
        : "r"(a[0]), "r"(a[1]), "r"(a[2]), "r"(a[3]), "r"(b0), "r"(b1));
}

__device__ __forceinline__ void split_pair(float a, float b, uint32_t& hi, uint32_t& lo) {
    __nv_bfloat16 ha = __float2bfloat16_rn(a), hb = __float2bfloat16_rn(b);
    __nv_bfloat162 hw(ha, hb);
    __nv_bfloat162 lw(__float2bfloat16_rn(a - __bfloat162float(ha)),
                      __float2bfloat16_rn(b - __bfloat162float(hb)));
    hi = *(uint32_t*)&hw;
    lo = *(uint32_t*)&lw;
}

// ---------------- packed smem layout (same as R8) ----------------
#define KC 32
#define SBLK 2048
#define SEC_E (2 * SBLK)
#define CHUNK_E (4 * SEC_E)
#define SMEM_BYTES (2 * CHUNK_E * 2)   // 65536

__device__ __forceinline__ void sts_pairs(__nv_bfloat16* sec, int row, int h,
                                          const uint32_t* w) {
    __nv_bfloat16* p = sec + h * SBLK + row * 16;
    #pragma unroll
    for (int j = 0; j < 4; j++) {
        uint2 u; u.x = w[j]; u.y = w[j + 4];
        *(uint2*)(p + j * 4) = u;
    }
}

__device__ __forceinline__ void compute_sub(const __nv_bfloat16* __restrict__ sbuf, int s,
                                            int lane, int wm, int wn, float acc[2][8][4]) {
    const int gid = lane >> 2, tig = lane & 3;
    const __nv_bfloat16* sA  = sbuf + s * SBLK;
    const __nv_bfloat16* sAl = sA + SEC_E;
    const __nv_bfloat16* sB  = sbuf + 2 * SEC_E + s * SBLK;
    const __nv_bfloat16* sBl = sB + SEC_E;
    const int qo = tig * 4;

    uint32_t ah[2][4], al[2][4];
    #pragma unroll
    for (int mt = 0; mt < 2; mt++) {
        const int r = wm * 32 + mt * 16 + gid;
        uint2 x0 = *(const uint2*)(sA + r * 16 + qo);
        uint2 x1 = *(const uint2*)(sA + (r + 8) * 16 + qo);
        ah[mt][0] = x0.x; ah[mt][1] = x1.x; ah[mt][2] = x0.y; ah[mt][3] = x1.y;
        uint2 y0 = *(const uint2*)(sAl + r * 16 + qo);
        uint2 y1 = *(const uint2*)(sAl + (r + 8) * 16 + qo);
        al[mt][0] = y0.x; al[mt][1] = y1.x; al[mt][2] = y0.y; al[mt][3] = y1.y;
    }

    #pragma unroll
    for (int nt = 0; nt < 8; nt++) {
        const int n = wn * 64 + nt * 8 + gid;
        uint2 bh = *(const uint2*)(sB + n * 16 + qo);
        uint2 bl = *(const uint2*)(sBl + n * 16 + qo);
        #pragma unroll
        for (int mt = 0; mt < 2; mt++) {
            float* d = acc[mt][nt];
            mma_bf16(d, ah[mt], bh.x, bh.y);
            mma_bf16(d, ah[mt], bl.x, bl.y);
            mma_bf16(d, al[mt], bh.x, bh.y);
        }
    }
}

// ---------------- GEMM1: H = silu(X @ W1) -> bf16 hi/lo (unchanged R8) --------
__global__ __launch_bounds__(256, 2) void gemm1_mma_kernel(
    const float* __restrict__ X, const float* __restrict__ W1)
{
    extern __shared__ __align__(16) __nv_bfloat16 sm[];
    const int tid = threadIdx.x, lane = tid & 31, wid = tid >> 5;
    const int wm = wid & 3, wn = wid >> 2;
    const int m0 = blockIdx.y * 128, n0 = blockIdx.x * 128;

    const int ar = tid >> 1, ahalf = tid & 1;
    const int bn = tid >> 1, bhalf = tid & 1;

    float4 va[4];
    float fb[16];

    float acc[2][8][4] = {};
    const int CH = Dn / KC;

    #define G1_LDG(c) {                                                          \
        const float* ap = X + (size_t)(m0 + ar) * Dn + (c) * KC + ahalf * 16;    \
        va[0] = *(const float4*)(ap);                                            \
        va[1] = *(const float4*)(ap + 4);                                        \
        va[2] = *(const float4*)(ap + 8);                                        \
        va[3] = *(const float4*)(ap + 12);                                       \
        const float* bp = W1 + (size_t)((c) * KC + bhalf * 16) * Hn + n0 + bn;   \
        _Pragma("unroll")                                                        \
        for (int kk = 0; kk < 16; kk++) fb[kk] = bp[(size_t)kk * Hn];            \
    }

    #define G1_STS(buf) {                                                        \
        __nv_bfloat16* base = sm + (buf) * CHUNK_E;                              \
        uint32_t whi[8], wlo[8];                                                 \
        _Pragma("unroll")                                                        \
        for (int j = 0; j < 4; j++) {                                            \
            split_pair(va[j].x, va[j].y, whi[2*j], wlo[2*j]);                    \
            split_pair(va[j].z, va[j].w, whi[2*j+1], wlo[2*j+1]);                \
        }                                                                        \
        sts_pairs(base,         ar, ahalf, whi);                                 \
        sts_pairs(base + SEC_E, ar, ahalf, wlo);                                 \
        _Pragma("unroll")                                                        \
        for (int tw = 0; tw < 8; tw++)                                           \
            split_pair(fb[2*tw], fb[2*tw+1], whi[tw], wlo[tw]);                  \
        sts_pairs(base + 2*SEC_E, bn, bhalf, whi);                               \
        sts_pairs(base + 3*SEC_E, bn, bhalf, wlo);                               \
    }

    G1_LDG(0);
    G1_STS(0);
    __syncthreads();

    for (int c = 0; c < CH; c++) {
        const bool hn = (c + 1 < CH);
        if (hn) G1_LDG(c + 1);
        compute_sub(sm + (c & 1) * CHUNK_E, 0, lane, wm, wn, acc);
        if (hn) G1_STS((c + 1) & 1);
        compute_sub(sm + (c & 1) * CHUNK_E, 1, lane, wm, wn, acc);
        __syncthreads();
    }

    #pragma unroll
    for (int mt = 0; mt < 2; mt++) {
        const int r = m0 + wm * 32 + mt * 16 + (lane >> 2);
        #pragma unroll
        for (int nt = 0; nt < 8; nt++) {
            const int c = n0 + wn * 64 + nt * 8 + (lane & 3) * 2;
            float f0 = silu_f(acc[mt][nt][0]);
            float f1 = silu_f(acc[mt][nt][1]);
            float f2 = silu_f(acc[mt][nt][2]);
            float f3 = silu_f(acc[mt][nt][3]);
            uint32_t h01, l01, h23, l23;
            split_pair(f0, f1, h01, l01);
            split_pair(f2, f3, h23, l23);
            *(uint32_t*)(g_hhi + (size_t)r * Hn + c)       = h01;
            *(uint32_t*)(g_hlo + (size_t)r * Hn + c)       = l01;
            *(uint32_t*)(g_hhi + (size_t)(r + 8) * Hn + c) = h23;
            *(uint32_t*)(g_hlo + (size_t)(r + 8) * Hn + c) = l23;
        }
    }
}

// ---------------- GEMM2: flat = H @ W2 + b2; fused conv + silu ----------------
#define XSP 36   // padded fp32 row stride for epilogue smem tiles

__global__ __launch_bounds__(256, 2) void gemm2_mma_kernel(
    const float* __restrict__ X, const float* __restrict__ W2,
    const float* __restrict__ B2, float* __restrict__ OUT)
{
    extern __shared__ __align__(16) __nv_bfloat16 sm[];
    const int tid = threadIdx.x, lane = tid & 31, wid = tid >> 5;
    const int wm = wid & 3, wn = wid >> 2;
    const int m0 = blockIdx.y * 128, n0 = blockIdx.x * 128;

    const int ar = tid >> 1, ahalf = tid & 1;
    const int bn = tid & 127, bhalf = tid >> 7;   // coalesced B LDG: 128B/warp

    uint4 ua0, ua1, ul0, ul1;
    float fb[16];

    float acc[2][8][4] = {};
    const int CH = Hn / KC;   // 8

    #define G2_LDG(c) {                                                          \
        const size_t aoff = (size_t)(m0 + ar) * Hn + (c) * KC + ahalf * 16;      \
        ua0 = *(const uint4*)(g_hhi + aoff);                                     \
        ua1 = *(const uint4*)(g_hhi + aoff + 8);                                 \
        ul0 = *(const uint4*)(g_hlo + aoff);                                     \
        ul1 = *(const uint4*)(g_hlo + aoff + 8);                                 \
        const float* bp = W2 + (size_t)((c) * KC + bhalf * 16) * N2 + n0 + bn;   \
        _Pragma("unroll")                                                        \
        for (int kk = 0; kk < 16; kk++) fb[kk] = bp[(size_t)kk * N2];            \
    }

    #define G2_STS(buf) {                                                        \
        __nv_bfloat16* base = sm + (buf) * CHUNK_E;                              \
        __nv_bfloat16* ph = base + ahalf * SBLK + ar * 16;                       \
        *(uint2*)(ph + 0)  = make_uint2(ua0.x, ua1.x);                           \
        *(uint2*)(ph + 4)  = make_uint2(ua0.y, ua1.y);                           \
        *(uint2*)(ph + 8)  = make_uint2(ua0.z, ua1.z);                           \
        *(uint2*)(ph + 12) = make_uint2(ua0.w, ua1.w);                           \
        __nv_bfloat16* pl = base + SEC_E + ahalf * SBLK + ar * 16;               \
        *(uint2*)(pl + 0)  = make_uint2(ul0.x, ul1.x);                           \
        *(uint2*)(pl + 4)  = make_uint2(ul0.y, ul1.y);                           \
        *(uint2*)(pl + 8)  = make_uint2(ul0.z, ul1.z);                           \
        *(uint2*)(pl + 12) = make_uint2(ul0.w, ul1.w);                           \
        uint32_t whi[8], wlo[8];                                                 \
        _Pragma("unroll")                                                        \
        for (int tw = 0; tw < 8; tw++)                                           \
            split_pair(fb[2*tw], fb[2*tw+1], whi[tw], wlo[tw]);                  \
        sts_pairs(base + 2*SEC_E, bn, bhalf, whi);                               \
        sts_pairs(base + 3*SEC_E, bn, bhalf, wlo);                               \
    }

    G2_LDG(0);
    G2_STS(0);
    __syncthreads();

    for (int c = 0; c < CH; c++) {
        const bool hn = (c + 1 < CH);
        if (hn) G2_LDG(c + 1);
        compute_sub(sm + (c & 1) * CHUNK_E, 0, lane, wm, wn, acc);
        if (hn) G2_STS((c + 1) & 1);
        compute_sub(sm + (c & 1) * CHUNK_E, 1, lane, wm, wn, acc);
        __syncthreads();
    }

    // ---- Epilogue: smem-staged X window / bias / OUT tile ----
    float* fs = (float*)sm;
    float* xs = fs;                    // [131][XSP] X window (rows m0-3 .. m0+127)
    float* os = fs + 131 * XSP;        // [128][XSP] output tile
    float* bs = os + 128 * XSP;        // [128] bias slice
    const int d0 = n0 >> 2;            // first of 32 channels for this CTA
    const int brow = (m0 / Tn) * Tn;   // batch base row (CTA never spans a batch)

    for (int i = tid; i < 131 * 8; i += 256) {
        const int rw = i >> 3, c4 = (i & 7) * 4;
        const int gr = m0 - 3 + rw;
        float4 v = make_float4(0.f, 0.f, 0.f, 0.f);
        if (gr >= brow) v = *(const float4*)(X + (size_t)gr * Dn + d0 + c4);
        *(float4*)(xs + rw * XSP + c4) = v;
    }
    if (tid < 128) bs[tid] = B2[n0 + tid];
    __syncthreads();

    const int q = lane & 3;
    #pragma unroll
    for (int mt = 0; mt < 2; mt++) {
        const int rb = wm * 32 + mt * 16 + (lane >> 2);   // local row
        #pragma unroll
        for (int nt = 0; nt < 8; nt++) {
            const int colb = wn * 64 + nt * 8;            // local flat col
            const int col0 = colb + q * 2;
            const float bb0 = bs[col0], bb1 = bs[col0 + 1];
            float c0 = acc[mt][nt][0] + bb0;
            float c1 = acc[mt][nt][1] + bb1;
            float c2 = acc[mt][nt][2] + bb0;
            float c3 = acc[mt][nt][3] + bb1;
            float o0 = __shfl_xor_sync(0xffffffffu, c0, 1);
            float o1 = __shfl_xor_sync(0xffffffffu, c1, 1);
            float o2 = __shfl_xor_sync(0xffffffffu, c2, 1);
            float o3 = __shfl_xor_sync(0xffffffffu, c3, 1);

            float k0, k1, k2, k3;
            int rloc;
            if ((q & 1) == 0) { rloc = rb;     k0 = c0; k1 = c1; k2 = o0; k3 = o1; }
            else              { rloc = rb + 8; k0 = o2; k1 = o3; k2 = c2; k3 = c3; }
            const int dloc = (colb >> 2) + (q >> 1);      // local channel 0..31

            // xs row j holds global row m0-3+j; output local row rloc taps j = rloc+w
            const float* xp = xs + rloc * XSP + dloc;
            float o = k0 * xp[0] + k1 * xp[XSP] + k2 * xp[2 * XSP] + k3 * xp[3 * XSP];
            os[rloc * XSP + dloc] = silu_f(o);
        }
    }
    __syncthreads();

    for (int i = tid; i < 128 * 8; i += 256) {
        const int rw = i >> 3, c4 = (i & 7) * 4;
        *(float4*)(OUT + (size_t)(m0 + rw) * Dn + d0 + c4) = *(float4*)(os + rw * XSP + c4);
    }
}

// ---------------- launch ----------------
extern "C" void kernel_launch(void* const* d_in, const int* in_sizes, int n_in,
                              void* d_out, int out_size) {
    const float* x  = (const float*)d_in[0];   // [4,4096,2048]
    const float* w1 = (const float*)d_in[1];   // [2048,256]
    const float* w2 = (const float*)d_in[2];   // [256,8192]
    const float* b2 = (const float*)d_in[3];   // [8192]
    float* out = (float*)d_out;

    cudaFuncSetAttribute(gemm1_mma_kernel,
                         cudaFuncAttributeMaxDynamicSharedMemorySize, SMEM_BYTES);
    cudaFuncSetAttribute(gemm2_mma_kernel,
                         cudaFuncAttributeMaxDynamicSharedMemorySize, SMEM_BYTES);

    gemm1_mma_kernel<<<dim3(Hn / 128, Mn / 128), 256, SMEM_BYTES>>>(x, w1);
    gemm2_mma_kernel<<<dim3(N2 / 128, Mn / 128), 256, SMEM_BYTES>>>(x, w2, b2, out);
}

// round 11
// speedup vs baseline: 2.1152x; 1.0267x over previous
#include <cuda_runtime.h>
#include <cuda_bf16.h>
#include <stdint.h>

// ---------------- problem constants ----------------
#define Bn 4
#define Tn 4096
#define Dn 2048
#define Hn 256
#define Wn 4
#define Mn (Bn * Tn)        // 16384
#define N2 (Dn * Wn)        // 8192

// Intermediates written by gemm1 (proven producer), read by gemm2.
__device__ __nv_bfloat16 g_hhi[(size_t)Mn * Hn];
__device__ __nv_bfloat16 g_hlo[(size_t)Mn * Hn];
// W2 packed hi/lo smem-image: per (n-block, k-chunk) [Bhi 4096][Blo 4096] elems.
__device__ __nv_bfloat16 g_w2p[(size_t)(N2 / 128) * (Hn / 32) * 8192];   // 8MB

__device__ __forceinline__ float silu_f(float v) { return v / (1.0f + __expf(-v)); }

__device__ __forceinline__ void mma_bf16(float* d, const uint32_t* a,
                                         uint32_t b0, uint32_t b1) {
    asm volatile(
        "mma.sync.aligned.m16n8k16.row.col.f32.bf16.bf16.f32 "
        "{%0,%1,%2,%3}, {%4,%5,%6,%7}, {%8,%9}, {%0,%1,%2,%3};"
        : "+f"(d[0]), "+f"(d[1]), "+f"(d[2]), "+f"(d[3])
        : "r"(a[0]), "r"(a[1]), "r"(a[2]), "r"(a[3]), "r"(b0), "r"(b1));
}

__device__ __forceinline__ void split_pair(float a, float b, uint32_t& hi, uint32_t& lo) {
    __nv_bfloat16 ha = __float2bfloat16_rn(a), hb = __float2bfloat16_rn(b);
    __nv_bfloat162 hw(ha, hb);
    __nv_bfloat162 lw(__float2bfloat16_rn(a - __bfloat162float(ha)),
                      __float2bfloat16_rn(b - __bfloat162float(hb)));
    hi = *(uint32_t*)&hw;
    lo = *(uint32_t*)&lw;
}

// ---------------- packed smem layout (same as R8/R9) ----------------
#define KC 32
#define SBLK 2048
#define SEC_E (2 * SBLK)
#define CHUNK_E (4 * SEC_E)
#define SMEM_BYTES (2 * CHUNK_E * 2)   // 65536

__device__ __forceinline__ void sts_pairs(__nv_bfloat16* sec, int row, int h,
                                          const uint32_t* w) {
    __nv_bfloat16* p = sec + h * SBLK + row * 16;
    #pragma unroll
    for (int j = 0; j < 4; j++) {
        uint2 u; u.x = w[j]; u.y = w[j + 4];
        *(uint2*)(p + j * 4) = u;
    }
}

// ---------------- fragment compute (byte-identical to R8/R9) ----------------
__device__ __forceinline__ void compute_sub(const __nv_bfloat16* __restrict__ sbuf, int s,
                                            int lane, int wm, int wn, float acc[2][8][4]) {
    const int gid = lane >> 2, tig = lane & 3;
    const __nv_bfloat16* sA  = sbuf + s * SBLK;
    const __nv_bfloat16* sAl = sA + SEC_E;
    const __nv_bfloat16* sB  = sbuf + 2 * SEC_E + s * SBLK;
    const __nv_bfloat16* sBl = sB + SEC_E;
    const int qo = tig * 4;

    uint32_t ah[2][4], al[2][4];
    #pragma unroll
    for (int mt = 0; mt < 2; mt++) {
        const int r = wm * 32 + mt * 16 + gid;
        uint2 x0 = *(const uint2*)(sA + r * 16 + qo);
        uint2 x1 = *(const uint2*)(sA + (r + 8) * 16 + qo);
        ah[mt][0] = x0.x; ah[mt][1] = x1.x; ah[mt][2] = x0.y; ah[mt][3] = x1.y;
        uint2 y0 = *(const uint2*)(sAl + r * 16 + qo);
        uint2 y1 = *(const uint2*)(sAl + (r + 8) * 16 + qo);
        al[mt][0] = y0.x; al[mt][1] = y1.x; al[mt][2] = y0.y; al[mt][3] = y1.y;
    }

    #pragma unroll
    for (int nt = 0; nt < 8; nt++) {
        const int n = wn * 64 + nt * 8 + gid;
        uint2 bh = *(const uint2*)(sB + n * 16 + qo);
        uint2 bl = *(const uint2*)(sBl + n * 16 + qo);
        #pragma unroll
        for (int mt = 0; mt < 2; mt++) {
            float* d = acc[mt][nt];
            mma_bf16(d, ah[mt], bh.x, bh.y);
            mma_bf16(d, ah[mt], bl.x, bl.y);
            mma_bf16(d, al[mt], bh.x, bh.y);
        }
    }
}

// ---------------- GEMM1: H = silu(X @ W1) -> bf16 hi/lo; also packs W2 --------
__global__ __launch_bounds__(256, 2) void gemm1_mma_kernel(
    const float* __restrict__ X, const float* __restrict__ W1,
    const float* __restrict__ W2)
{
    extern __shared__ __align__(16) __nv_bfloat16 sm[];
    const int tid = threadIdx.x, lane = tid & 31, wid = tid >> 5;
    const int wm = wid & 3, wn = wid >> 2;
    const int m0 = blockIdx.y * 128, n0 = blockIdx.x * 128;

    const int ar = tid >> 1, ahalf = tid & 1;
    const int bn = tid >> 1, bhalf = tid & 1;

    float4 va[4];
    float fb[16];

    float acc[2][8][4] = {};
    const int CH = Dn / KC;

    #define G1_LDG(c) {                                                          \
        const float* ap = X + (size_t)(m0 + ar) * Dn + (c) * KC + ahalf * 16;    \
        va[0] = *(const float4*)(ap);                                            \
        va[1] = *(const float4*)(ap + 4);                                        \
        va[2] = *(const float4*)(ap + 8);                                        \
        va[3] = *(const float4*)(ap + 12);                                       \
        const float* bp = W1 + (size_t)((c) * KC + bhalf * 16) * Hn + n0 + bn;   \
        _Pragma("unroll")                                                        \
        for (int kk = 0; kk < 16; kk++) fb[kk] = bp[(size_t)kk * Hn];            \
    }

    #define G1_STS(buf) {                                                        \
        __nv_bfloat16* base = sm + (buf) * CHUNK_E;                              \
        uint32_t whi[8], wlo[8];                                                 \
        _Pragma("unroll")                                                        \
        for (int j = 0; j < 4; j++) {                                            \
            split_pair(va[j].x, va[j].y, whi[2*j], wlo[2*j]);                    \
            split_pair(va[j].z, va[j].w, whi[2*j+1], wlo[2*j+1]);                \
        }                                                                        \
        sts_pairs(base,         ar, ahalf, whi);                                 \
        sts_pairs(base + SEC_E, ar, ahalf, wlo);                                 \
        _Pragma("unroll")                                                        \
        for (int tw = 0; tw < 8; tw++)                                           \
            split_pair(fb[2*tw], fb[2*tw+1], whi[tw], wlo[tw]);                  \
        sts_pairs(base + 2*SEC_E, bn, bhalf, whi);                               \
        sts_pairs(base + 3*SEC_E, bn, bhalf, wlo);                               \
    }

    G1_LDG(0);
    G1_STS(0);
    __syncthreads();

    for (int c = 0; c < CH; c++) {
        const bool hn = (c + 1 < CH);
        if (hn) G1_LDG(c + 1);
        compute_sub(sm + (c & 1) * CHUNK_E, 0, lane, wm, wn, acc);
        if (hn) G1_STS((c + 1) & 1);
        compute_sub(sm + (c & 1) * CHUNK_E, 1, lane, wm, wn, acc);
        __syncthreads();
    }

    #pragma unroll
    for (int mt = 0; mt < 2; mt++) {
        const int r = m0 + wm * 32 + mt * 16 + (lane >> 2);
        #pragma unroll
        for (int nt = 0; nt < 8; nt++) {
            const int c = n0 + wn * 64 + nt * 8 + (lane & 3) * 2;
            float f0 = silu_f(acc[mt][nt][0]);
            float f1 = silu_f(acc[mt][nt][1]);
            float f2 = silu_f(acc[mt][nt][2]);
            float f3 = silu_f(acc[mt][nt][3]);
            uint32_t h01, l01, h23, l23;
            split_pair(f0, f1, h01, l01);
            split_pair(f2, f3, h23, l23);
            *(uint32_t*)(g_hhi + (size_t)r * Hn + c)       = h01;
            *(uint32_t*)(g_hlo + (size_t)r * Hn + c)       = l01;
            *(uint32_t*)(g_hhi + (size_t)(r + 8) * Hn + c) = h23;
            *(uint32_t*)(g_hlo + (size_t)(r + 8) * Hn + c) = l23;
        }
    }

    // ---- Pack W2 [256, 8192] fp32 -> g_w2p hi/lo smem-image ----
    // 256 CTAs x 256 threads x 16 items cover all (kp, n) pairs (128 x 8192).
    // Placement mirrors sts_pairs: word t at (t&3)*4 + (t>>2)*2.
    {
        const int gtid = (blockIdx.y * gridDim.x + blockIdx.x) * 256 + tid;
        #pragma unroll
        for (int it = 0; it < 16; it++) {
            const int pid = gtid + it * 65536;
            const int n = pid & (N2 - 1);
            const int k = (pid >> 13) * 2;
            uint32_t hi, lo;
            split_pair(W2[(size_t)k * N2 + n], W2[(size_t)(k + 1) * N2 + n], hi, lo);
            const int nb = n >> 7, nloc = n & 127;
            const int c = k >> 5, s = (k >> 4) & 1, t = (k >> 1) & 7;
            const size_t base = (size_t)(nb * (Hn / KC) + c) * 8192
                              + s * SBLK + nloc * 16 + (t & 3) * 4 + (t >> 2) * 2;
            *(uint32_t*)(g_w2p + base)        = hi;
            *(uint32_t*)(g_w2p + base + 4096) = lo;
        }
    }
}

// ---------------- GEMM2: flat = H @ W2 + b2; fused conv + silu ----------------
#define XSP 36

__global__ __launch_bounds__(256, 2) void gemm2_mma_kernel(
    const float* __restrict__ X, const float* __restrict__ B2,
    float* __restrict__ OUT)
{
    extern __shared__ __align__(16) __nv_bfloat16 sm[];
    const int tid = threadIdx.x, lane = tid & 31, wid = tid >> 5;
    const int wm = wid & 3, wn = wid >> 2;
    const int m0 = blockIdx.y * 128, n0 = blockIdx.x * 128;
    const int nb = blockIdx.x;

    const int ar = tid >> 1, ahalf = tid & 1;

    uint4 ua0, ua1, ul0, ul1;
    uint4 vb[4];

    float acc[2][8][4] = {};
    const int CH = Hn / KC;   // 8

    #define G2_LDG(c) {                                                          \
        const size_t aoff = (size_t)(m0 + ar) * Hn + (c) * KC + ahalf * 16;      \
        ua0 = *(const uint4*)(g_hhi + aoff);                                     \
        ua1 = *(const uint4*)(g_hhi + aoff + 8);                                 \
        ul0 = *(const uint4*)(g_hlo + aoff);                                     \
        ul1 = *(const uint4*)(g_hlo + aoff + 8);                                 \
        const __nv_bfloat16* wp = g_w2p + (size_t)(nb * CH + (c)) * 8192;        \
        _Pragma("unroll")                                                        \
        for (int j = 0; j < 4; j++)                                              \
            vb[j] = *(const uint4*)(wp + (tid + j * 256) * 8);                   \
    }

    #define G2_STS(buf) {                                                        \
        __nv_bfloat16* base = sm + (buf) * CHUNK_E;                              \
        __nv_bfloat16* ph = base + ahalf * SBLK + ar * 16;                       \
        *(uint2*)(ph + 0)  = make_uint2(ua0.x, ua1.x);                           \
        *(uint2*)(ph + 4)  = make_uint2(ua0.y, ua1.y);                           \
        *(uint2*)(ph + 8)  = make_uint2(ua0.z, ua1.z);                           \
        *(uint2*)(ph + 12) = make_uint2(ua0.w, ua1.w);                           \
        __nv_bfloat16* pl = base + SEC_E + ahalf * SBLK + ar * 16;               \
        *(uint2*)(pl + 0)  = make_uint2(ul0.x, ul1.x);                           \
        *(uint2*)(pl + 4)  = make_uint2(ul0.y, ul1.y);                           \
        *(uint2*)(pl + 8)  = make_uint2(ul0.z, ul1.z);                           \
        *(uint2*)(pl + 12) = make_uint2(ul0.w, ul1.w);                           \
        _Pragma("unroll")                                                        \
        for (int j = 0; j < 4; j++)                                              \
            *(uint4*)(base + 2 * SEC_E + (tid + j * 256) * 8) = vb[j];           \
    }

    G2_LDG(0);
    G2_STS(0);
    __syncthreads();

    for (int c = 0; c < CH; c++) {
        const bool hn = (c + 1 < CH);
        if (hn) G2_LDG(c + 1);
        compute_sub(sm + (c & 1) * CHUNK_E, 0, lane, wm, wn, acc);
        if (hn) G2_STS((c + 1) & 1);
        compute_sub(sm + (c & 1) * CHUNK_E, 1, lane, wm, wn, acc);
        __syncthreads();
    }

    // ---- Epilogue (verbatim R9): smem-staged X window / bias / OUT tile ----
    float* fs = (float*)sm;
    float* xs = fs;
    float* os = fs + 131 * XSP;
    float* bs = os + 128 * XSP;
    const int d0 = n0 >> 2;
    const int brow = (m0 / Tn) * Tn;

    for (int i = tid; i < 131 * 8; i += 256) {
        const int rw = i >> 3, c4 = (i & 7) * 4;
        const int gr = m0 - 3 + rw;
        float4 v = make_float4(0.f, 0.f, 0.f, 0.f);
        if (gr >= brow) v = *(const float4*)(X + (size_t)gr * Dn + d0 + c4);
        *(float4*)(xs + rw * XSP + c4) = v;
    }
    if (tid < 128) bs[tid] = B2[n0 + tid];
    __syncthreads();

    const int q = lane & 3;
    #pragma unroll
    for (int mt = 0; mt < 2; mt++) {
        const int rb = wm * 32 + mt * 16 + (lane >> 2);
        #pragma unroll
        for (int nt = 0; nt < 8; nt++) {
            const int colb = wn * 64 + nt * 8;
            const int col0 = colb + q * 2;
            const float bb0 = bs[col0], bb1 = bs[col0 + 1];
            float c0 = acc[mt][nt][0] + bb0;
            float c1 = acc[mt][nt][1] + bb1;
            float c2 = acc[mt][nt][2] + bb0;
            float c3 = acc[mt][nt][3] + bb1;
            float o0 = __shfl_xor_sync(0xffffffffu, c0, 1);
            float o1 = __shfl_xor_sync(0xffffffffu, c1, 1);
            float o2 = __shfl_xor_sync(0xffffffffu, c2, 1);
            float o3 = __shfl_xor_sync(0xffffffffu, c3, 1);

            float k0, k1, k2, k3;
            int rloc;
            if ((q & 1) == 0) { rloc = rb;     k0 = c0; k1 = c1; k2 = o0; k3 = o1; }
            else              { rloc = rb + 8; k0 = o2; k1 = o3; k2 = c2; k3 = c3; }
            const int dloc = (colb >> 2) + (q >> 1);

            const float* xp = xs + rloc * XSP + dloc;
            float o = k0 * xp[0] + k1 * xp[XSP] + k2 * xp[2 * XSP] + k3 * xp[3 * XSP];
            os[rloc * XSP + dloc] = silu_f(o);
        }
    }
    __syncthreads();

    for (int i = tid; i < 128 * 8; i += 256) {
        const int rw = i >> 3, c4 = (i & 7) * 4;
        *(float4*)(OUT + (size_t)(m0 + rw) * Dn + d0 + c4) = *(float4*)(os + rw * XSP + c4);
    }
}

// ---------------- launch ----------------
extern "C" void kernel_launch(void* const* d_in, const int* in_sizes, int n_in,
                              void* d_out, int out_size) {
    const float* x  = (const float*)d_in[0];   // [4,4096,2048]
    const float* w1 = (const float*)d_in[1];   // [2048,256]
    const float* w2 = (const float*)d_in[2];   // [256,8192]
    const float* b2 = (const float*)d_in[3];   // [8192]
    float* out = (float*)d_out;

    cudaFuncSetAttribute(gemm1_mma_kernel,
                         cudaFuncAttributeMaxDynamicSharedMemorySize, SMEM_BYTES);
    cudaFuncSetAttribute(gemm2_mma_kernel,
                         cudaFuncAttributeMaxDynamicSharedMemorySize, SMEM_BYTES);

    gemm1_mma_kernel<<<dim3(Hn / 128, Mn / 128), 256, SMEM_BYTES>>>(x, w1, w2);
    gemm2_mma_kernel<<<dim3(N2 / 128, Mn / 128), 256, SMEM_BYTES>>>(x, b2, out);
}

// round 12
// speedup vs baseline: 2.8138x; 1.3303x over previous
#include <cuda_runtime.h>
#include <cuda_bf16.h>
#include <stdint.h>

// ---------------- problem constants ----------------
#define Bn 4
#define Tn 4096
#define Dn 2048
#define Hn 256
#define Wn 4
#define Mn (Bn * Tn)        // 16384
#define N2 (Dn * Wn)        // 8192

// Packed smem-image intermediates (written by gemm1, read by gemm2).
// Per (block, k-chunk) image: [hi 4096 elems][lo 4096 elems] = 16KB.
__device__ __nv_bfloat16 g_hpack[(size_t)(Mn / 128) * (Hn / 32) * 8192];  // 16.8MB
__device__ __nv_bfloat16 g_w2p[(size_t)(N2 / 128) * (Hn / 32) * 8192];    // 8MB

__device__ __forceinline__ float silu_f(float v) { return v / (1.0f + __expf(-v)); }

__device__ __forceinline__ uint32_t s2u(const void* p) {
    return (uint32_t)__cvta_generic_to_shared(p);
}

__device__ __forceinline__ void cp_async16(uint32_t saddr, const void* gaddr) {
    asm volatile("cp.async.cg.shared.global [%0], [%1], 16;" :: "r"(saddr), "l"(gaddr));
}
#define CP_COMMIT()  asm volatile("cp.async.commit_group;" ::: "memory")
#define CP_WAIT(N)   asm volatile("cp.async.wait_group %0;" :: "n"(N) : "memory")

__device__ __forceinline__ void mma_bf16(float* d, const uint32_t* a,
                                         uint32_t b0, uint32_t b1) {
    asm volatile(
        "mma.sync.aligned.m16n8k16.row.col.f32.bf16.bf16.f32 "
        "{%0,%1,%2,%3}, {%4,%5,%6,%7}, {%8,%9}, {%0,%1,%2,%3};"
        : "+f"(d[0]), "+f"(d[1]), "+f"(d[2]), "+f"(d[3])
        : "r"(a[0]), "r"(a[1]), "r"(a[2]), "r"(a[3]), "r"(b0), "r"(b1));
}

__device__ __forceinline__ void split_pair(float a, float b, uint32_t& hi, uint32_t& lo) {
    __nv_bfloat16 ha = __float2bfloat16_rn(a), hb = __float2bfloat16_rn(b);
    __nv_bfloat162 hw(ha, hb);
    __nv_bfloat162 lw(__float2bfloat16_rn(a - __bfloat162float(ha)),
                      __float2bfloat16_rn(b - __bfloat162float(hb)));
    hi = *(uint32_t*)&hw;
    lo = *(uint32_t*)&lw;
}

// ---------------- packed smem layout (same as R8-R11) ----------------
#define KC 32
#define SBLK 2048
#define SEC_E (2 * SBLK)               // 4096
#define CHUNK_E (4 * SEC_E)            // 16384 elems = 32KB
#define G1_SMEM (2 * CHUNK_E * 2)      // 65536
#define PIPE 3
#define G2_SMEM (PIPE * CHUNK_E * 2)   // 98304

__device__ __forceinline__ void sts_pairs(__nv_bfloat16* sec, int row, int h,
                                          const uint32_t* w) {
    __nv_bfloat16* p = sec + h * SBLK + row * 16;
    #pragma unroll
    for (int j = 0; j < 4; j++) {
        uint2 u; u.x = w[j]; u.y = w[j + 4];
        *(uint2*)(p + j * 4) = u;
    }
}

// ---------------- fragment compute (byte-identical to R8-R11) ----------------
__device__ __forceinline__ void compute_sub(const __nv_bfloat16* __restrict__ sbuf, int s,
                                            int lane, int wm, int wn, float acc[2][8][4]) {
    const int gid = lane >> 2, tig = lane & 3;
    const __nv_bfloat16* sA  = sbuf + s * SBLK;
    const __nv_bfloat16* sAl = sA + SEC_E;
    const __nv_bfloat16* sB  = sbuf + 2 * SEC_E + s * SBLK;
    const __nv_bfloat16* sBl = sB + SEC_E;
    const int qo = tig * 4;

    uint32_t ah[2][4], al[2][4];
    #pragma unroll
    for (int mt = 0; mt < 2; mt++) {
        const int r = wm * 32 + mt * 16 + gid;
        uint2 x0 = *(const uint2*)(sA + r * 16 + qo);
        uint2 x1 = *(const uint2*)(sA + (r + 8) * 16 + qo);
        ah[mt][0] = x0.x; ah[mt][1] = x1.x; ah[mt][2] = x0.y; ah[mt][3] = x1.y;
        uint2 y0 = *(const uint2*)(sAl + r * 16 + qo);
        uint2 y1 = *(const uint2*)(sAl + (r + 8) * 16 + qo);
        al[mt][0] = y0.x; al[mt][1] = y1.x; al[mt][2] = y0.y; al[mt][3] = y1.y;
    }

    #pragma unroll
    for (int nt = 0; nt < 8; nt++) {
        const int n = wn * 64 + nt * 8 + gid;
        uint2 bh = *(const uint2*)(sB + n * 16 + qo);
        uint2 bl = *(const uint2*)(sBl + n * 16 + qo);
        #pragma unroll
        for (int mt = 0; mt < 2; mt++) {
            float* d = acc[mt][nt];
            mma_bf16(d, ah[mt], bh.x, bh.y);
            mma_bf16(d, ah[mt], bl.x, bl.y);
            mma_bf16(d, al[mt], bh.x, bh.y);
        }
    }
}

// ---------------- GEMM1: H = silu(X @ W1) -> packed image; also packs W2 ------
__global__ __launch_bounds__(256, 2) void gemm1_mma_kernel(
    const float* __restrict__ X, const float* __restrict__ W1,
    const float* __restrict__ W2)
{
    extern __shared__ __align__(16) __nv_bfloat16 sm[];
    const int tid = threadIdx.x, lane = tid & 31, wid = tid >> 5;
    const int wm = wid & 3, wn = wid >> 2;
    const int m0 = blockIdx.y * 128, n0 = blockIdx.x * 128;

    const int ar = tid >> 1, ahalf = tid & 1;
    const int bn = tid >> 1, bhalf = tid & 1;

    float4 va[4];
    float fb[16];

    float acc[2][8][4] = {};
    const int CH = Dn / KC;

    #define G1_LDG(c) {                                                          \
        const float* ap = X + (size_t)(m0 + ar) * Dn + (c) * KC + ahalf * 16;    \
        va[0] = *(const float4*)(ap);                                            \
        va[1] = *(const float4*)(ap + 4);                                        \
        va[2] = *(const float4*)(ap + 8);                                        \
        va[3] = *(const float4*)(ap + 12);                                       \
        const float* bp = W1 + (size_t)((c) * KC + bhalf * 16) * Hn + n0 + bn;   \
        _Pragma("unroll")                                                        \
        for (int kk = 0; kk < 16; kk++) fb[kk] = bp[(size_t)kk * Hn];            \
    }

    #define G1_STS(buf) {                                                        \
        __nv_bfloat16* base = sm + (buf) * CHUNK_E;                              \
        uint32_t whi[8], wlo[8];                                                 \
        _Pragma("unroll")                                                        \
        for (int j = 0; j < 4; j++) {                                            \
            split_pair(va[j].x, va[j].y, whi[2*j], wlo[2*j]);                    \
            split_pair(va[j].z, va[j].w, whi[2*j+1], wlo[2*j+1]);                \
        }                                                                        \
        sts_pairs(base,         ar, ahalf, whi);                                 \
        sts_pairs(base + SEC_E, ar, ahalf, wlo);                                 \
        _Pragma("unroll")                                                        \
        for (int tw = 0; tw < 8; tw++)                                           \
            split_pair(fb[2*tw], fb[2*tw+1], whi[tw], wlo[tw]);                  \
        sts_pairs(base + 2*SEC_E, bn, bhalf, whi);                               \
        sts_pairs(base + 3*SEC_E, bn, bhalf, wlo);                               \
    }

    G1_LDG(0);
    G1_STS(0);
    __syncthreads();

    for (int c = 0; c < CH; c++) {
        const bool hn = (c + 1 < CH);
        if (hn) G1_LDG(c + 1);
        compute_sub(sm + (c & 1) * CHUNK_E, 0, lane, wm, wn, acc);
        if (hn) G1_STS((c + 1) & 1);
        compute_sub(sm + (c & 1) * CHUNK_E, 1, lane, wm, wn, acc);
        __syncthreads();
    }

    // ---- Epilogue: silu -> H written in packed smem-image layout ----
    // H element at (row r, k-col kcol): chunk cc=kcol>>5, s=(kcol>>4)&1,
    // word t=(kcol>>1)&7 at elem s*2048 + rloc*16 + (t&3)*4 + (t>>2)*2.
    {
        const int mb1 = blockIdx.y;
        #pragma unroll
        for (int mt = 0; mt < 2; mt++) {
            const int r1 = wm * 32 + mt * 16 + (lane >> 2);
            #pragma unroll
            for (int nt = 0; nt < 8; nt++) {
                const int kcol = n0 + wn * 64 + nt * 8 + (lane & 3) * 2;
                const int cc = kcol >> 5, ss = (kcol >> 4) & 1, tt = (kcol >> 1) & 7;
                const size_t go = (size_t)(mb1 * (Hn / KC) + cc) * 8192
                                + ss * SBLK + (tt & 3) * 4 + (tt >> 2) * 2;
                float f0 = silu_f(acc[mt][nt][0]);
                float f1 = silu_f(acc[mt][nt][1]);
                float f2 = silu_f(acc[mt][nt][2]);
                float f3 = silu_f(acc[mt][nt][3]);
                uint32_t h01, l01, h23, l23;
                split_pair(f0, f1, h01, l01);
                split_pair(f2, f3, h23, l23);
                *(uint32_t*)(g_hpack + go + r1 * 16)              = h01;
                *(uint32_t*)(g_hpack + go + r1 * 16 + 4096)       = l01;
                *(uint32_t*)(g_hpack + go + (r1 + 8) * 16)        = h23;
                *(uint32_t*)(g_hpack + go + (r1 + 8) * 16 + 4096) = l23;
            }
        }
    }

    // ---- Pack W2 [256, 8192] fp32 -> g_w2p hi/lo smem-image (proven R11) ----
    {
        const int gtid = (blockIdx.y * gridDim.x + blockIdx.x) * 256 + tid;
        #pragma unroll
        for (int it = 0; it < 16; it++) {
            const int pid = gtid + it * 65536;
            const int n = pid & (N2 - 1);
            const int k = (pid >> 13) * 2;
            uint32_t hi, lo;
            split_pair(W2[(size_t)k * N2 + n], W2[(size_t)(k + 1) * N2 + n], hi, lo);
            const int nb = n >> 7, nloc = n & 127;
            const int c = k >> 5, s = (k >> 4) & 1, t = (k >> 1) & 7;
            const size_t base = (size_t)(nb * (Hn / KC) + c) * 8192
                              + s * SBLK + nloc * 16 + (t & 3) * 4 + (t >> 2) * 2;
            *(uint32_t*)(g_w2p + base)        = hi;
            *(uint32_t*)(g_w2p + base + 4096) = lo;
        }
    }
}

// ---------------- GEMM2: flat = H @ W2 + b2; fused conv + silu ----------------
#define XSP 36

__global__ __launch_bounds__(256, 2) void gemm2_mma_kernel(
    const float* __restrict__ X, const float* __restrict__ B2,
    float* __restrict__ OUT)
{
    extern __shared__ __align__(16) __nv_bfloat16 sm[];
    const int tid = threadIdx.x, lane = tid & 31, wid = tid >> 5;
    const int wm = wid & 3, wn = wid >> 2;
    const int m0 = blockIdx.y * 128, n0 = blockIdx.x * 128;
    const int nb = blockIdx.x, mb = blockIdx.y;
    const uint32_t sbase = s2u(sm);
    const int CH = Hn / KC;   // 8

    float acc[2][8][4] = {};

    // Async copy of one chunk's A+B packed images into pipeline buffer.
    #define G2_COPY(c) {                                                         \
        const __nv_bfloat16* ap = g_hpack + (size_t)(mb * CH + (c)) * 8192;      \
        const __nv_bfloat16* bp = g_w2p  + (size_t)(nb * CH + (c)) * 8192;       \
        const uint32_t db = sbase + ((c) % PIPE) * (CHUNK_E * 2);                \
        _Pragma("unroll")                                                        \
        for (int j = 0; j < 4; j++)                                              \
            cp_async16(db + (tid + j * 256) * 16, ap + (tid + j * 256) * 8);     \
        _Pragma("unroll")                                                        \
        for (int j = 0; j < 4; j++)                                              \
            cp_async16(db + 2 * SEC_E * 2 + (tid + j * 256) * 16,                \
                       bp + (tid + j * 256) * 8);                                \
        CP_COMMIT();                                                             \
    }

    G2_COPY(0);
    G2_COPY(1);

    #pragma unroll
    for (int c = 0; c < CH; c++) {
        if (c < CH - 1) { CP_WAIT(1); } else { CP_WAIT(0); }
        __syncthreads();
        const __nv_bfloat16* buf = sm + (c % PIPE) * CHUNK_E;
        compute_sub(buf, 0, lane, wm, wn, acc);
        compute_sub(buf, 1, lane, wm, wn, acc);
        __syncthreads();
        if (c + PIPE - 1 < CH) G2_COPY(c + PIPE - 1);
    }

    // ---- Epilogue (verbatim R9/R11): smem-staged X window / bias / OUT ----
    float* fs = (float*)sm;
    float* xs = fs;
    float* os = fs + 131 * XSP;
    float* bs = os + 128 * XSP;
    const int d0 = n0 >> 2;
    const int brow = (m0 / Tn) * Tn;

    for (int i = tid; i < 131 * 8; i += 256) {
        const int rw = i >> 3, c4 = (i & 7) * 4;
        const int gr = m0 - 3 + rw;
        float4 v = make_float4(0.f, 0.f, 0.f, 0.f);
        if (gr >= brow) v = *(const float4*)(X + (size_t)gr * Dn + d0 + c4);
        *(float4*)(xs + rw * XSP + c4) = v;
    }
    if (tid < 128) bs[tid] = B2[n0 + tid];
    __syncthreads();

    const int q = lane & 3;
    #pragma unroll
    for (int mt = 0; mt < 2; mt++) {
        const int rb = wm * 32 + mt * 16 + (lane >> 2);
        #pragma unroll
        for (int nt = 0; nt < 8; nt++) {
            const int colb = wn * 64 + nt * 8;
            const int col0 = colb + q * 2;
            const float bb0 = bs[col0], bb1 = bs[col0 + 1];
            float c0 = acc[mt][nt][0] + bb0;
            float c1 = acc[mt][nt][1] + bb1;
            float c2 = acc[mt][nt][2] + bb0;
            float c3 = acc[mt][nt][3] + bb1;
            float o0 = __shfl_xor_sync(0xffffffffu, c0, 1);
            float o1 = __shfl_xor_sync(0xffffffffu, c1, 1);
            float o2 = __shfl_xor_sync(0xffffffffu, c2, 1);
            float o3 = __shfl_xor_sync(0xffffffffu, c3, 1);

            float k0, k1, k2, k3;
            int rloc;
            if ((q & 1) == 0) { rloc = rb;     k0 = c0; k1 = c1; k2 = o0; k3 = o1; }
            else              { rloc = rb + 8; k0 = o2; k1 = o3; k2 = c2; k3 = c3; }
            const int dloc = (colb >> 2) + (q >> 1);

            const float* xp = xs + rloc * XSP + dloc;
            float o = k0 * xp[0] + k1 * xp[XSP] + k2 * xp[2 * XSP] + k3 * xp[3 * XSP];
            os[rloc * XSP + dloc] = silu_f(o);
        }
    }
    __syncthreads();

    for (int i = tid; i < 128 * 8; i += 256) {
        const int rw = i >> 3, c4 = (i & 7) * 4;
        *(float4*)(OUT + (size_t)(m0 + rw) * Dn + d0 + c4) = *(float4*)(os + rw * XSP + c4);
    }
}

// ---------------- launch ----------------
extern "C" void kernel_launch(void* const* d_in, const int* in_sizes, int n_in,
                              void* d_out, int out_size) {
    const float* x  = (const float*)d_in[0];   // [4,4096,2048]
    const float* w1 = (const float*)d_in[1];   // [2048,256]
    const float* w2 = (const float*)d_in[2];   // [256,8192]
    const float* b2 = (const float*)d_in[3];   // [8192]
    float* out = (float*)d_out;

    cudaFuncSetAttribute(gemm1_mma_kernel,
                         cudaFuncAttributeMaxDynamicSharedMemorySize, G1_SMEM);
    cudaFuncSetAttribute(gemm2_mma_kernel,
                         cudaFuncAttributeMaxDynamicSharedMemorySize, G2_SMEM);

    gemm1_mma_kernel<<<dim3(Hn / 128, Mn / 128), 256, G1_SMEM>>>(x, w1, w2);
    gemm2_mma_kernel<<<dim3(N2 / 128, Mn / 128), 256, G2_SMEM>>>(x, b2, out);
}

// round 13
// speedup vs baseline: 2.8504x; 1.0130x over previous
#include <cuda_runtime.h>
#include <cuda_bf16.h>
#include <stdint.h>

// ---------------- problem constants ----------------
#define Bn 4
#define Tn 4096
#define Dn 2048
#define Hn 256
#define Wn 4
#define Mn (Bn * Tn)        // 16384
#define N2 (Dn * Wn)        // 8192

// Packed hi/lo smem-image intermediates. Image per (block, k-chunk):
// [hi 4096 elems][lo 4096 elems] = 16KB.
__device__ __nv_bfloat16 g_xpack[(size_t)(Mn / 128) * (Dn / 32) * 8192];  // 128MB
__device__ __nv_bfloat16 g_w1p[(size_t)(Hn / 128) * (Dn / 32) * 8192];    // 2MB
__device__ __nv_bfloat16 g_hpack[(size_t)(Mn / 128) * (Hn / 32) * 8192];  // 16.8MB
__device__ __nv_bfloat16 g_w2p[(size_t)(N2 / 128) * (Hn / 32) * 8192];    // 8MB

// Global barrier state (reset by last CTA each call -> graph-replay safe).
__device__ unsigned g_barIn = 0;
__device__ unsigned g_barOut = 0;

__device__ __forceinline__ float silu_f(float v) { return v / (1.0f + __expf(-v)); }

__device__ __forceinline__ uint32_t s2u(const void* p) {
    return (uint32_t)__cvta_generic_to_shared(p);
}

__device__ __forceinline__ void cp_async16(uint32_t saddr, const void* gaddr) {
    asm volatile("cp.async.cg.shared.global [%0], [%1], 16;" :: "r"(saddr), "l"(gaddr));
}
#define CP_COMMIT()  asm volatile("cp.async.commit_group;" ::: "memory")
#define CP_WAIT(N)   asm volatile("cp.async.wait_group %0;" :: "n"(N) : "memory")

__device__ __forceinline__ void mma_bf16(float* d, const uint32_t* a,
                                         uint32_t b0, uint32_t b1) {
    asm volatile(
        "mma.sync.aligned.m16n8k16.row.col.f32.bf16.bf16.f32 "
        "{%0,%1,%2,%3}, {%4,%5,%6,%7}, {%8,%9}, {%0,%1,%2,%3};"
        : "+f"(d[0]), "+f"(d[1]), "+f"(d[2]), "+f"(d[3])
        : "r"(a[0]), "r"(a[1]), "r"(a[2]), "r"(a[3]), "r"(b0), "r"(b1));
}

__device__ __forceinline__ void split_pair(float a, float b, uint32_t& hi, uint32_t& lo) {
    __nv_bfloat16 ha = __float2bfloat16_rn(a), hb = __float2bfloat16_rn(b);
    __nv_bfloat162 hw(ha, hb);
    __nv_bfloat162 lw(__float2bfloat16_rn(a - __bfloat162float(ha)),
                      __float2bfloat16_rn(b - __bfloat162float(hb)));
    hi = *(uint32_t*)&hw;
    lo = *(uint32_t*)&lw;
}

// ---------------- packed smem layout (same as R8-R12) ----------------
#define KC 32
#define SBLK 2048
#define SEC_E (2 * SBLK)               // 4096
#define CHUNK_E (4 * SEC_E)            // 16384 elems = 32KB
#define PIPE 3
#define GEMM_SMEM (PIPE * CHUNK_E * 2) // 98304

// Write word-pairs (t, t+4) adjacent; works for shared or global dst.
__device__ __forceinline__ void sts_pairs(__nv_bfloat16* sec, int row, int h,
                                          const uint32_t* w) {
    __nv_bfloat16* p = sec + h * SBLK + row * 16;
    #pragma unroll
    for (int j = 0; j < 4; j++) {
        uint2 u; u.x = w[j]; u.y = w[j + 4];
        *(uint2*)(p + j * 4) = u;
    }
}

// ---------------- fragment compute (byte-identical to R8-R12) ----------------
__device__ __forceinline__ void compute_sub(const __nv_bfloat16* __restrict__ sbuf, int s,
                                            int lane, int wm, int wn, float acc[2][8][4]) {
    const int gid = lane >> 2, tig = lane & 3;
    const __nv_bfloat16* sA  = sbuf + s * SBLK;
    const __nv_bfloat16* sAl = sA + SEC_E;
    const __nv_bfloat16* sB  = sbuf + 2 * SEC_E + s * SBLK;
    const __nv_bfloat16* sBl = sB + SEC_E;
    const int qo = tig * 4;

    uint32_t ah[2][4], al[2][4];
    #pragma unroll
    for (int mt = 0; mt < 2; mt++) {
        const int r = wm * 32 + mt * 16 + gid;
        uint2 x0 = *(const uint2*)(sA + r * 16 + qo);
        uint2 x1 = *(const uint2*)(sA + (r + 8) * 16 + qo);
        ah[mt][0] = x0.x; ah[mt][1] = x1.x; ah[mt][2] = x0.y; ah[mt][3] = x1.y;
        uint2 y0 = *(const uint2*)(sAl + r * 16 + qo);
        uint2 y1 = *(const uint2*)(sAl + (r + 8) * 16 + qo);
        al[mt][0] = y0.x; al[mt][1] = y1.x; al[mt][2] = y0.y; al[mt][3] = y1.y;
    }

    #pragma unroll
    for (int nt = 0; nt < 8; nt++) {
        const int n = wn * 64 + nt * 8 + gid;
        uint2 bh = *(const uint2*)(sB + n * 16 + qo);
        uint2 bl = *(const uint2*)(sBl + n * 16 + qo);
        #pragma unroll
        for (int mt = 0; mt < 2; mt++) {
            float* d = acc[mt][nt];
            mma_bf16(d, ah[mt], bh.x, bh.y);
            mma_bf16(d, ah[mt], bl.x, bl.y);
            mma_bf16(d, al[mt], bh.x, bh.y);
        }
    }
}

// ---------------- GEMM1: phaseA pack(X,W1,W2) + barrier + async mainloop ------
#define NCT 256

__global__ __launch_bounds__(256, 2) void gemm1_mma_kernel(
    const float* __restrict__ X, const float* __restrict__ W1,
    const float* __restrict__ W2)
{
    extern __shared__ __align__(16) __nv_bfloat16 sm[];
    const int tid = threadIdx.x, lane = tid & 31, wid = tid >> 5;
    const int wm = wid & 3, wn = wid >> 2;
    const int nb = blockIdx.x, mb = blockIdx.y;
    const int m0 = mb * 128, n0 = nb * 128;
    const uint32_t sbase = s2u(sm);

    // ===== Phase A: cooperative packing =====
    // X m-block: this CTA packs chunks [nb*32, nb*32+32).
    {
        const int row = tid >> 1, khalf = tid & 1;
        for (int cc = nb * 32; cc < nb * 32 + 32; cc++) {
            const float* ap = X + (size_t)(m0 + row) * Dn + cc * KC + khalf * 16;
            float4 va0 = *(const float4*)(ap);
            float4 va1 = *(const float4*)(ap + 4);
            float4 va2 = *(const float4*)(ap + 8);
            float4 va3 = *(const float4*)(ap + 12);
            uint32_t whi[8], wlo[8];
            split_pair(va0.x, va0.y, whi[0], wlo[0]);
            split_pair(va0.z, va0.w, whi[1], wlo[1]);
            split_pair(va1.x, va1.y, whi[2], wlo[2]);
            split_pair(va1.z, va1.w, whi[3], wlo[3]);
            split_pair(va2.x, va2.y, whi[4], wlo[4]);
            split_pair(va2.z, va2.w, whi[5], wlo[5]);
            split_pair(va3.x, va3.y, whi[6], wlo[6]);
            split_pair(va3.z, va3.w, whi[7], wlo[7]);
            __nv_bfloat16* base = g_xpack + (size_t)(mb * (Dn / KC) + cc) * 8192;
            sts_pairs(base,        row, khalf, whi);
            sts_pairs(base + SEC_E, row, khalf, wlo);
        }
    }
    // W1 pack: 4 items/thread across all CTAs (262144 (kp, n) pairs).
    {
        const int gtid = (mb * 2 + nb) * 256 + tid;
        #pragma unroll
        for (int it = 0; it < 4; it++) {
            const int pid = gtid + it * 65536;
            const int n = pid & (Hn - 1);
            const int k = (pid >> 8) * 2;
            uint32_t hi, lo;
            split_pair(W1[(size_t)k * Hn + n], W1[(size_t)(k + 1) * Hn + n], hi, lo);
            const int nbk = n >> 7, nloc = n & 127;
            const int c = k >> 5, s = (k >> 4) & 1, t = (k >> 1) & 7;
            const size_t base = (size_t)(nbk * (Dn / KC) + c) * 8192
                              + s * SBLK + nloc * 16 + (t & 3) * 4 + (t >> 2) * 2;
            *(uint32_t*)(g_w1p + base)        = hi;
            *(uint32_t*)(g_w1p + base + 4096) = lo;
        }
    }
    // W2 pack (proven R11/R12 formula): 16 items/thread.
    {
        const int gtid = (mb * 2 + nb) * 256 + tid;
        #pragma unroll
        for (int it = 0; it < 16; it++) {
            const int pid = gtid + it * 65536;
            const int n = pid & (N2 - 1);
            const int k = (pid >> 13) * 2;
            uint32_t hi, lo;
            split_pair(W2[(size_t)k * N2 + n], W2[(size_t)(k + 1) * N2 + n], hi, lo);
            const int nbk = n >> 7, nloc = n & 127;
            const int c = k >> 5, s = (k >> 4) & 1, t = (k >> 1) & 7;
            const size_t base = (size_t)(nbk * (Hn / KC) + c) * 8192
                              + s * SBLK + nloc * 16 + (t & 3) * 4 + (t >> 2) * 2;
            *(uint32_t*)(g_w2p + base)        = hi;
            *(uint32_t*)(g_w2p + base + 4096) = lo;
        }
    }

    // ===== Global barrier (all 256 CTAs resident: 148 SMs x 2) =====
    __syncthreads();
    if (tid == 0) {
        __threadfence();
        atomicAdd(&g_barIn, 1u);
        while (*(volatile unsigned*)&g_barIn < NCT) { }
        __threadfence();
        unsigned d = atomicAdd(&g_barOut, 1u) + 1;
        if (d == NCT) {               // last CTA resets for next graph replay
            *(volatile unsigned*)&g_barIn = 0;
            __threadfence();
            *(volatile unsigned*)&g_barOut = 0;
        }
    }
    __syncthreads();

    // ===== Phase B: cp.async pipelined mainloop (CH = 64) =====
    float acc[2][8][4] = {};
    const int CH = Dn / KC;

    #define G1_COPY(c) {                                                         \
        const __nv_bfloat16* ap = g_xpack + (size_t)(mb * CH + (c)) * 8192;      \
        const __nv_bfloat16* bp = g_w1p   + (size_t)(nb * CH + (c)) * 8192;      \
        const uint32_t db = sbase + ((c) % PIPE) * (CHUNK_E * 2);                \
        _Pragma("unroll")                                                        \
        for (int j = 0; j < 4; j++)                                              \
            cp_async16(db + (tid + j * 256) * 16, ap + (tid + j * 256) * 8);     \
        _Pragma("unroll")                                                        \
        for (int j = 0; j < 4; j++)                                              \
            cp_async16(db + 2 * SEC_E * 2 + (tid + j * 256) * 16,                \
                       bp + (tid + j * 256) * 8);                                \
        CP_COMMIT();                                                             \
    }

    G1_COPY(0);
    G1_COPY(1);
    for (int c = 0; c < CH; c++) {
        if (c < CH - 1) { CP_WAIT(1); } else { CP_WAIT(0); }
        __syncthreads();
        if (c + 2 < CH) G1_COPY(c + 2);
        const __nv_bfloat16* buf = sm + (c % PIPE) * CHUNK_E;
        compute_sub(buf, 0, lane, wm, wn, acc);
        compute_sub(buf, 1, lane, wm, wn, acc);
    }

    // ---- Epilogue (verbatim R12): silu -> H in packed smem-image layout ----
    #pragma unroll
    for (int mt = 0; mt < 2; mt++) {
        const int r1 = wm * 32 + mt * 16 + (lane >> 2);
        #pragma unroll
        for (int nt = 0; nt < 8; nt++) {
            const int kcol = n0 + wn * 64 + nt * 8 + (lane & 3) * 2;
            const int cc = kcol >> 5, ss = (kcol >> 4) & 1, tt = (kcol >> 1) & 7;
            const size_t go = (size_t)(mb * (Hn / KC) + cc) * 8192
                            + ss * SBLK + (tt & 3) * 4 + (tt >> 2) * 2;
            float f0 = silu_f(acc[mt][nt][0]);
            float f1 = silu_f(acc[mt][nt][1]);
            float f2 = silu_f(acc[mt][nt][2]);
            float f3 = silu_f(acc[mt][nt][3]);
            uint32_t h01, l01, h23, l23;
            split_pair(f0, f1, h01, l01);
            split_pair(f2, f3, h23, l23);
            *(uint32_t*)(g_hpack + go + r1 * 16)              = h01;
            *(uint32_t*)(g_hpack + go + r1 * 16 + 4096)       = l01;
            *(uint32_t*)(g_hpack + go + (r1 + 8) * 16)        = h23;
            *(uint32_t*)(g_hpack + go + (r1 + 8) * 16 + 4096) = l23;
        }
    }
}

// ---------------- GEMM2: flat = H @ W2 + b2; fused conv + silu ----------------
#define XSP 36

__global__ __launch_bounds__(256, 2) void gemm2_mma_kernel(
    const float* __restrict__ X, const float* __restrict__ B2,
    float* __restrict__ OUT)
{
    extern __shared__ __align__(16) __nv_bfloat16 sm[];
    const int tid = threadIdx.x, lane = tid & 31, wid = tid >> 5;
    const int wm = wid & 3, wn = wid >> 2;
    const int m0 = blockIdx.y * 128, n0 = blockIdx.x * 128;
    const int nb = blockIdx.x, mb = blockIdx.y;
    const uint32_t sbase = s2u(sm);
    const int CH = Hn / KC;   // 8

    float acc[2][8][4] = {};

    #define G2_COPY(c) {                                                         \
        const __nv_bfloat16* ap = g_hpack + (size_t)(mb * CH + (c)) * 8192;      \
        const __nv_bfloat16* bp = g_w2p  + (size_t)(nb * CH + (c)) * 8192;       \
        const uint32_t db = sbase + ((c) % PIPE) * (CHUNK_E * 2);                \
        _Pragma("unroll")                                                        \
        for (int j = 0; j < 4; j++)                                              \
            cp_async16(db + (tid + j * 256) * 16, ap + (tid + j * 256) * 8);     \
        _Pragma("unroll")                                                        \
        for (int j = 0; j < 4; j++)                                              \
            cp_async16(db + 2 * SEC_E * 2 + (tid + j * 256) * 16,                \
                       bp + (tid + j * 256) * 8);                                \
        CP_COMMIT();                                                             \
    }

    G2_COPY(0);
    G2_COPY(1);

    #pragma unroll
    for (int c = 0; c < CH; c++) {
        if (c < CH - 1) { CP_WAIT(1); } else { CP_WAIT(0); }
        __syncthreads();
        if (c + 2 < CH) G2_COPY(c + 2);
        const __nv_bfloat16* buf = sm + (c % PIPE) * CHUNK_E;
        compute_sub(buf, 0, lane, wm, wn, acc);
        compute_sub(buf, 1, lane, wm, wn, acc);
    }
    __syncthreads();   // smem about to be reused by the epilogue tiles

    // ---- Epilogue (verbatim R9-R12): smem-staged X window / bias / OUT ----
    float* fs = (float*)sm;
    float* xs = fs;
    float* os = fs + 131 * XSP;
    float* bs = os + 128 * XSP;
    const int d0 = n0 >> 2;
    const int brow = (m0 / Tn) * Tn;

    for (int i = tid; i < 131 * 8; i += 256) {
        const int rw = i >> 3, c4 = (i & 7) * 4;
        const int gr = m0 - 3 + rw;
        float4 v = make_float4(0.f, 0.f, 0.f, 0.f);
        if (gr >= brow) v = *(const float4*)(X + (size_t)gr * Dn + d0 + c4);
        *(float4*)(xs + rw * XSP + c4) = v;
    }
    if (tid < 128) bs[tid] = B2[n0 + tid];
    __syncthreads();

    const int q = lane & 3;
    #pragma unroll
    for (int mt = 0; mt < 2; mt++) {
        const int rb = wm * 32 + mt * 16 + (lane >> 2);
        #pragma unroll
        for (int nt = 0; nt < 8; nt++) {
            const int colb = wn * 64 + nt * 8;
            const int col0 = colb + q * 2;
            const float bb0 = bs[col0], bb1 = bs[col0 + 1];
            float c0 = acc[mt][nt][0] + bb0;
            float c1 = acc[mt][nt][1] + bb1;
            float c2 = acc[mt][nt][2] + bb0;
            float c3 = acc[mt][nt][3] + bb1;
            float o0 = __shfl_xor_sync(0xffffffffu, c0, 1);
            float o1 = __shfl_xor_sync(0xffffffffu, c1, 1);
            float o2 = __shfl_xor_sync(0xffffffffu, c2, 1);
            float o3 = __shfl_xor_sync(0xffffffffu, c3, 1);

            float k0, k1, k2, k3;
            int rloc;
            if ((q & 1) == 0) { rloc = rb;     k0 = c0; k1 = c1; k2 = o0; k3 = o1; }
            else              { rloc = rb + 8; k0 = o2; k1 = o3; k2 = c2; k3 = c3; }
            const int dloc = (colb >> 2) + (q >> 1);

            const float* xp = xs + rloc * XSP + dloc;
            float o = k0 * xp[0] + k1 * xp[XSP] + k2 * xp[2 * XSP] + k3 * xp[3 * XSP];
            os[rloc * XSP + dloc] = silu_f(o);
        }
    }
    __syncthreads();

    for (int i = tid; i < 128 * 8; i += 256) {
        const int rw = i >> 3, c4 = (i & 7) * 4;
        *(float4*)(OUT + (size_t)(m0 + rw) * Dn + d0 + c4) = *(float4*)(os + rw * XSP + c4);
    }
}

// ---------------- launch ----------------
extern "C" void kernel_launch(void* const* d_in, const int* in_sizes, int n_in,
                              void* d_out, int out_size) {
    const float* x  = (const float*)d_in[0];   // [4,4096,2048]
    const float* w1 = (const float*)d_in[1];   // [2048,256]
    const float* w2 = (const float*)d_in[2];   // [256,8192]
    const float* b2 = (const float*)d_in[3];   // [8192]
    float* out = (float*)d_out;

    cudaFuncSetAttribute(gemm1_mma_kernel,
                         cudaFuncAttributeMaxDynamicSharedMemorySize, GEMM_SMEM);
    cudaFuncSetAttribute(gemm2_mma_kernel,
                         cudaFuncAttributeMaxDynamicSharedMemorySize, GEMM_SMEM);

    gemm1_mma_kernel<<<dim3(Hn / 128, Mn / 128), 256, GEMM_SMEM>>>(x, w1, w2);
    gemm2_mma_kernel<<<dim3(N2 / 128, Mn / 128), 256, GEMM_SMEM>>>(x, b2, out);
}